// round 14
// baseline (speedup 1.0000x reference)
#include <cuda_runtime.h>
#include <cstdint>

// Problem constants
#define NN    2048          // meta nodes
#define MDIM  64            // subgraph nodes
#define DDIM  64            // channels
#define FDIM  4096          // MDIM*DDIM
#define OUTD  64
#define LN_EPS 1e-5f

// ------------------------- scratch (device globals; no allocation) ----------
__device__ float g_Af[NN * NN];     // A (row-major)
__device__ float g_AT[NN * NN];     // A^T
__device__ float g_A2[NN * NN];     // (A^2)^T
__device__ float g_A3[NN * NN];     // (A^3)^T
__device__ float g_X [NN * FDIM];
__device__ float g_B1[NN * FDIM];
__device__ float g_B2[NN * FDIM];
__device__ float g_B3[NN * FDIM];
__device__ float g_Sn[MDIM * MDIM];

// ------------- cast + transpose-cast in one pass: Af and AT ------------------
__global__ void cast_both(const int* __restrict__ a, float* __restrict__ Af,
                          float* __restrict__ AT) {
    __shared__ float tile[32][33];
    int bx = blockIdx.x * 32, by = blockIdx.y * 32;
    int tx = threadIdx.x, ty = threadIdx.y;            // 32x8
    #pragma unroll
    for (int j = 0; j < 32; j += 8) {
        float v = (float)a[(long)(by + ty + j) * NN + bx + tx];
        Af[(long)(by + ty + j) * NN + bx + tx] = v;
        tile[ty + j][tx] = v;
    }
    __syncthreads();
    #pragma unroll
    for (int j = 0; j < 32; j += 8)
        AT[(long)(bx + ty + j) * NN + by + tx] = tile[tx][ty + j];
}

// ------------------------- Sn = D^-1/2 (S+I) D^-1/2 (256 threads) -----------
__global__ void compute_sn(const int* __restrict__ sub_adj, float* __restrict__ Sn) {
    __shared__ float part[MDIM][4];
    __shared__ float dinv[MDIM];
    const int t = threadIdx.x;           // 256
    const int u = t >> 2, q = t & 3;
    float s = 0.0f;
    #pragma unroll
    for (int v = 0; v < 16; v++) s += (float)sub_adj[u * MDIM + q * 16 + v];
    part[u][q] = s;
    __syncthreads();
    if (q == 0)
        dinv[u] = rsqrtf(1.0f + part[u][0] + part[u][1] + part[u][2] + part[u][3]);
    __syncthreads();
    #pragma unroll
    for (int j = 0; j < 16; j++) {
        int idx = t + j * 256;           // 0..4095
        int uu = idx >> 6, vv = idx & 63;
        float a = (float)sub_adj[idx] + (uu == vv ? 1.0f : 0.0f);
        Sn[idx] = dinv[uu] * a * dinv[vv];
    }
}

// ------------------------- mma / cp.async / f32x2 helpers --------------------
__device__ __forceinline__ void mma_tf32(float c[4], const uint32_t a[4],
                                         const uint32_t b[2]) {
    asm volatile(
        "mma.sync.aligned.m16n8k8.row.col.f32.tf32.tf32.f32 "
        "{%0,%1,%2,%3}, {%4,%5,%6,%7}, {%8,%9}, {%0,%1,%2,%3};\n"
        : "+f"(c[0]), "+f"(c[1]), "+f"(c[2]), "+f"(c[3])
        : "r"(a[0]), "r"(a[1]), "r"(a[2]), "r"(a[3]), "r"(b[0]), "r"(b[1]));
}

__device__ __forceinline__ void cp16(float* smem, const float* gmem) {
    uint32_t s = (uint32_t)__cvta_generic_to_shared(smem);
    asm volatile("cp.async.cg.shared.global [%0], [%1], 16;\n" :: "r"(s), "l"(gmem));
}
__device__ __forceinline__ void cp_commit() {
    asm volatile("cp.async.commit_group;\n");
}
template<int W> __device__ __forceinline__ void cp_wait() {
    asm volatile("cp.async.wait_group %0;\n" :: "n"(W));
}

__device__ __forceinline__ unsigned long long pack2(float x) {
    unsigned long long r;
    asm("mov.b64 %0, {%1, %1};" : "=l"(r) : "f"(x));
    return r;
}
__device__ __forceinline__ unsigned long long pack2f(float lo, float hi) {
    unsigned long long r;
    asm("mov.b64 %0, {%1, %2};" : "=l"(r) : "f"(lo), "f"(hi));
    return r;
}
__device__ __forceinline__ void fma2(unsigned long long& d, unsigned long long a,
                                     unsigned long long b) {
    asm("fma.rn.f32x2 %0, %1, %2, %0;" : "+l"(d) : "l"(a), "l"(b));
}
__device__ __forceinline__ float2 unpack2(unsigned long long v) {
    float2 f;
    asm("mov.b64 {%0, %1}, %2;" : "=f"(f.x), "=f"(f.y) : "l"(v));
    return f;
}

// ---------------- tensor-core GEMM: C(MxN) = (AT)^T (MxK) * B(KxN) ----------
// (unchanged) CTA 256x128x32, 256 threads, warp tile 64x64, 4 stages.
#define TBM 256
#define TBN 128
#define TBK 32
#define STAGES 4
#define ASPAD 264
#define BSPAD 136
#define GEMM_SMEM (STAGES * TBK * (ASPAD + BSPAD) * 4)   // 204800 bytes

__global__ __launch_bounds__(256, 1)
void gemm_tt(const float* __restrict__ AT, const float* __restrict__ B,
             float* __restrict__ C, int M, int N, int K) {
    extern __shared__ float sm[];
    float (*As)[TBK][ASPAD] = (float (*)[TBK][ASPAD])sm;
    float (*Bs)[TBK][BSPAD] = (float (*)[TBK][BSPAD])(sm + STAGES * TBK * ASPAD);

    const int t  = threadIdx.x;               // 0..255
    const long bm = (long)blockIdx.y * TBM;
    const long bn = (long)blockIdx.x * TBN;
    const int lane = t & 31;
    const int g  = lane >> 2;                 // 0..7
    const int tg = lane & 3;                  // 0..3
    const int w  = t >> 5;                    // 0..7
    const int wm = (w >> 1) * 64;             // 0,64,128,192
    const int wn = (w & 1) * 64;              // 0 or 64

    const int akk = t >> 3;
    const int ac0 = (t & 7) * 4;
    const int asw = ((akk >> 4) & 1) << 4;
    const float* Ag = AT + (long)akk * M + bm;
    const int bkk = t >> 5;
    const int bn4 = (t & 31) * 4;
    const float* Bg = B + (long)bkk * N + bn + bn4;

    float c[4][8][4];
    #pragma unroll
    for (int im = 0; im < 4; im++)
        #pragma unroll
        for (int in = 0; in < 8; in++) {
            c[im][in][0] = 0.f; c[im][in][1] = 0.f;
            c[im][in][2] = 0.f; c[im][in][3] = 0.f;
        }

    const int ktiles = K / TBK;

    #pragma unroll
    for (int s = 0; s < STAGES - 1; s++) {
        const long k0 = (long)s * TBK;
        #pragma unroll
        for (int j = 0; j < 8; j++)
            cp16(&As[s][akk][(ac0 + 32 * j) ^ asw], Ag + k0 * M + ac0 + 32 * j);
        #pragma unroll
        for (int j = 0; j < 4; j++)
            cp16(&Bs[s][bkk + 8 * j][bn4], Bg + (k0 + 8 * j) * N);
        cp_commit();
    }

    for (int i = 0; i < ktiles; i++) {
        if (i + STAGES - 1 < ktiles) cp_wait<STAGES - 2>(); else cp_wait<0>();
        __syncthreads();

        const int nx = i + STAGES - 1;
        if (nx < ktiles) {
            const int st = nx & (STAGES - 1);
            const long k0 = (long)nx * TBK;
            #pragma unroll
            for (int j = 0; j < 8; j++)
                cp16(&As[st][akk][(ac0 + 32 * j) ^ asw], Ag + k0 * M + ac0 + 32 * j);
            #pragma unroll
            for (int j = 0; j < 4; j++)
                cp16(&Bs[st][bkk + 8 * j][bn4], Bg + (k0 + 8 * j) * N);
            cp_commit();
        }

        const int cur = i & (STAGES - 1);
        #pragma unroll
        for (int ks = 0; ks < 4; ks++) {
            const int kr = ks * 8;
            const int sw = (ks >> 1) << 4;
            uint32_t af[4][4], bf[8][2];
            #pragma unroll
            for (int im = 0; im < 4; im++) {
                const int m0 = (wm + im * 16 + g) ^ sw;
                const int m8 = (wm + im * 16 + g + 8) ^ sw;
                af[im][0] = __float_as_uint(As[cur][kr + tg    ][m0]);
                af[im][1] = __float_as_uint(As[cur][kr + tg    ][m8]);
                af[im][2] = __float_as_uint(As[cur][kr + tg + 4][m0]);
                af[im][3] = __float_as_uint(As[cur][kr + tg + 4][m8]);
            }
            #pragma unroll
            for (int in = 0; in < 8; in++) {
                const int nb = wn + in * 8 + g;
                bf[in][0] = __float_as_uint(Bs[cur][kr + tg    ][nb]);
                bf[in][1] = __float_as_uint(Bs[cur][kr + tg + 4][nb]);
            }
            #pragma unroll
            for (int im = 0; im < 4; im++)
                #pragma unroll
                for (int in = 0; in < 8; in++)
                    mma_tf32(c[im][in], af[im], bf[in]);
        }
    }

    #pragma unroll
    for (int im = 0; im < 4; im++) {
        const long row = bm + wm + im * 16 + g;
        #pragma unroll
        for (int in = 0; in < 8; in++) {
            const int col = bn + wn + in * 8 + 2 * tg;
            float* Cp = C + row * N + col;
            *(float2*)Cp           = make_float2(c[im][in][0], c[im][in][1]);
            *(float2*)(Cp + 8 * N) = make_float2(c[im][in][2], c[im][in][3]);
        }
    }
}

// ===== wsum_ln: T = sum_i Xi @ Wi (tensor tf32), then per-n Sn@T + b, LN, ReLU
// CTA = 256 rows = 4 complete n's. T kept in smem (reuses X staging buffer).
// MMA phase identical to proven wsum; LN phase identical to proven epilogue,
// looped over the 4 n-sub-blocks.
#define WSL_XT (256 * 68)
#define WSL_WT (64 * 68)
#define WSL_SMEM ((WSL_XT + 2 * WSL_WT) * 4)   // 104448 bytes

__global__ __launch_bounds__(256, 2)
void wsum_ln(const float* __restrict__ x0, const float* __restrict__ x1,
             const float* __restrict__ x2, const float* __restrict__ x3,
             const float* __restrict__ Wl,       // (4,64,64)
             const float* __restrict__ Sn,       // (64,64)
             const float* __restrict__ bconv_l,  // (4,64)
             const float* __restrict__ gamma_l,  // (64,64)
             const float* __restrict__ beta_l,   // (64,64)
             float* __restrict__ Xout) {
    extern __shared__ float wsm[];
    float (*Xs)[68]  = (float (*)[68])(wsm);                 // reused as T
    float (*Ws)[68]  = (float (*)[68])(wsm + WSL_XT);
    float (*Sns)[68] = (float (*)[68])(wsm + WSL_XT + WSL_WT);
    __shared__ float red[8];
    __shared__ float s_mu, s_rstd;

    const int t = threadIdx.x;
    const long r0 = (long)blockIdx.x * 256;
    const int lane = t & 31;
    const int g  = lane >> 2;        // 0..7
    const int tg = lane & 3;         // 0..3
    const int w  = t >> 5;
    const int wr = w >> 1;           // 0..3 : 64-row group
    const int wc = w & 1;            // 0..1 : 32-col group

    // stage Sn once (region disjoint from Xs/Ws; visible after first sync)
    #pragma unroll
    for (int i = 0; i < 16; i++) {
        int idx = t + i * 256;
        Sns[idx >> 6][idx & 63] = Sn[idx];
    }

    float c[4][4][4];
    #pragma unroll
    for (int im = 0; im < 4; im++)
        #pragma unroll
        for (int in = 0; in < 4; in++) {
            c[im][in][0] = 0.f; c[im][in][1] = 0.f;
            c[im][in][2] = 0.f; c[im][in][3] = 0.f;
        }

    const float* xs[4] = { x0, x1, x2, x3 };

    #pragma unroll
    for (int s = 0; s < 4; s++) {
        __syncthreads();                 // smem reuse guard
        #pragma unroll
        for (int j = 0; j < 16; j++) {
            int idx = t + 256 * j;
            int row = idx >> 4, c4 = (idx & 15) * 4;
            *(float4*)&Xs[row][c4] =
                *(const float4*)(xs[s] + (r0 + row) * 64 + c4);
        }
        #pragma unroll
        for (int j = 0; j < 4; j++) {
            int idx = t + 256 * j;
            int kr = idx >> 4, c4 = (idx & 15) * 4;
            *(float4*)&Ws[kr][c4] =
                *(const float4*)(Wl + s * 4096 + kr * 64 + c4);
        }
        __syncthreads();

        #pragma unroll
        for (int kc = 0; kc < 8; kc++) {
            const int kr = kc * 8;
            uint32_t ah[4][4], bh[4][2];
            #pragma unroll
            for (int im = 0; im < 4; im++) {
                const int rb = wr * 64 + im * 16 + g;
                ah[im][0] = __float_as_uint(Xs[rb    ][kr + tg]);
                ah[im][1] = __float_as_uint(Xs[rb + 8][kr + tg]);
                ah[im][2] = __float_as_uint(Xs[rb    ][kr + tg + 4]);
                ah[im][3] = __float_as_uint(Xs[rb + 8][kr + tg + 4]);
            }
            #pragma unroll
            for (int in = 0; in < 4; in++) {
                const int cb = wc * 32 + in * 8 + g;
                bh[in][0] = __float_as_uint(Ws[kr + tg    ][cb]);
                bh[in][1] = __float_as_uint(Ws[kr + tg + 4][cb]);
            }
            #pragma unroll
            for (int im = 0; im < 4; im++)
                #pragma unroll
                for (int in = 0; in < 4; in++)
                    mma_tf32(c[im][in], ah[im], bh[in]);
        }
    }

    // write T tile into Xs (staging buffer is dead now)
    __syncthreads();
    #pragma unroll
    for (int im = 0; im < 4; im++) {
        const int row = wr * 64 + im * 16 + g;
        #pragma unroll
        for (int in = 0; in < 4; in++) {
            const int col = wc * 32 + in * 8 + 2 * tg;
            *(float2*)&Xs[row][col]     = make_float2(c[im][in][0], c[im][in][1]);
            *(float2*)&Xs[row + 8][col] = make_float2(c[im][in][2], c[im][in][3]);
        }
    }
    __syncthreads();

    // ---------------- LN phase: 4 n's sequentially, all 256 threads each ----
    const int u = t >> 2;
    const int q = t & 3;
    const int lane2 = t & 31, wid = t >> 5;

    // hoisted per-thread constants
    unsigned long long hb[4][2];
    float4 g4[4], b4[4];
    #pragma unroll
    for (int v = 0; v < 4; v++) {
        #pragma unroll
        for (int jj = 0; jj < 2; jj++) {
            int cc = q * 4 + 16 * v + 2 * jj;
            float b0 = bconv_l[cc]       + bconv_l[64 + cc]
                     + bconv_l[128 + cc] + bconv_l[192 + cc];
            float b1 = bconv_l[cc + 1]       + bconv_l[64 + cc + 1]
                     + bconv_l[128 + cc + 1] + bconv_l[192 + cc + 1];
            hb[v][jj] = pack2f(b0, b1);
        }
        g4[v] = *(const float4*)(gamma_l + u * 64 + q * 4 + 16 * v);
        b4[v] = *(const float4*)(beta_l  + u * 64 + q * 4 + 16 * v);
    }

    for (int s4 = 0; s4 < 4; s4++) {
        unsigned long long h2[4][2];
        #pragma unroll
        for (int v = 0; v < 4; v++) { h2[v][0] = hb[v][0]; h2[v][1] = hb[v][1]; }

        #pragma unroll 8
        for (int k = 0; k < 64; k++) {
            unsigned long long sv = pack2(Sns[u][k]);
            #pragma unroll
            for (int v = 0; v < 4; v++) {
                ulonglong2 ww = *(const ulonglong2*)&Xs[s4 * 64 + k][q * 4 + 16 * v];
                fma2(h2[v][0], sv, ww.x);
                fma2(h2[v][1], sv, ww.y);
            }
        }

        float h[16];
        #pragma unroll
        for (int v = 0; v < 4; v++) {
            float2 a0 = unpack2(h2[v][0]);
            float2 a1 = unpack2(h2[v][1]);
            h[4 * v + 0] = a0.x; h[4 * v + 1] = a0.y;
            h[4 * v + 2] = a1.x; h[4 * v + 3] = a1.y;
        }

        float lsum = 0.0f;
        #pragma unroll
        for (int j = 0; j < 16; j++) lsum += h[j];
        #pragma unroll
        for (int o = 16; o > 0; o >>= 1) lsum += __shfl_xor_sync(0xffffffffu, lsum, o);
        if (lane2 == 0) red[wid] = lsum;
        __syncthreads();
        if (t == 0) {
            float s = 0.0f;
            #pragma unroll
            for (int i = 0; i < 8; i++) s += red[i];
            s_mu = s * (1.0f / 4096.0f);
        }
        __syncthreads();
        const float mu = s_mu;

        float lv = 0.0f;
        #pragma unroll
        for (int j = 0; j < 16; j++) { float d = h[j] - mu; lv += d * d; }
        #pragma unroll
        for (int o = 16; o > 0; o >>= 1) lv += __shfl_xor_sync(0xffffffffu, lv, o);
        if (lane2 == 0) red[wid] = lv;
        __syncthreads();
        if (t == 0) {
            float s = 0.0f;
            #pragma unroll
            for (int i = 0; i < 8; i++) s += red[i];
            s_rstd = rsqrtf(s * (1.0f / 4096.0f) + LN_EPS);
        }
        __syncthreads();
        const float rstd = s_rstd;

        float* xo = Xout + ((long)(blockIdx.x * 4 + s4)) * FDIM + u * 64;
        #pragma unroll
        for (int v = 0; v < 4; v++) {
            const int cc = q * 4 + 16 * v;
            float4 o;
            o.x = fmaxf((h[4 * v + 0] - mu) * rstd * g4[v].x + b4[v].x, 0.0f);
            o.y = fmaxf((h[4 * v + 1] - mu) * rstd * g4[v].y + b4[v].y, 0.0f);
            o.z = fmaxf((h[4 * v + 2] - mu) * rstd * g4[v].z + b4[v].z, 0.0f);
            o.w = fmaxf((h[4 * v + 3] - mu) * rstd * g4[v].w + b4[v].w, 0.0f);
            *(float4*)(xo + cc) = o;
        }
    }
}

// ----------- readout: out(2048,64) = X(2048,4096) @ Wl(4096,64) + bl --------
__global__ __launch_bounds__(256)
void final_gemm(const float* __restrict__ X, const float* __restrict__ Wl,
                const float* __restrict__ bl, float* __restrict__ out) {
    __shared__ float Xs[16][128];
    __shared__ float Ws[128][68];
    const int t = threadIdx.x;
    const long m0 = (long)blockIdx.x * 16;
    const int r  = t >> 4;
    const int cq = (t & 15) * 4;

    float acc[4] = {0.f, 0.f, 0.f, 0.f};

    for (int k0 = 0; k0 < FDIM; k0 += 128) {
        #pragma unroll
        for (int i = 0; i < 2; i++) {
            int idx = t + i * 256;
            int rr = idx >> 5, cc = (idx & 31) * 4;
            *(float4*)&Xs[rr][cc] = *(const float4*)(X + (m0 + rr) * FDIM + k0 + cc);
        }
        #pragma unroll
        for (int i = 0; i < 8; i++) {
            int idx = t + i * 256;
            int kk = idx >> 4, cc = (idx & 15) * 4;
            float4 v = *(const float4*)(Wl + (long)(k0 + kk) * 64 + cc);
            Ws[kk][cc] = v.x; Ws[kk][cc + 1] = v.y; Ws[kk][cc + 2] = v.z; Ws[kk][cc + 3] = v.w;
        }
        __syncthreads();
        #pragma unroll 16
        for (int kk = 0; kk < 128; kk++) {
            float xv = Xs[r][kk];
            #pragma unroll
            for (int j = 0; j < 4; j++) acc[j] += xv * Ws[kk][cq + j];
        }
        __syncthreads();
    }
    float4 v = make_float4(acc[0] + bl[cq], acc[1] + bl[cq + 1],
                           acc[2] + bl[cq + 2], acc[3] + bl[cq + 3]);
    *(float4*)(out + (m0 + r) * 64 + cq) = v;
}

// ---------------------------------------------------------------------------
extern "C" void kernel_launch(void* const* d_in, const int* in_sizes, int n_in,
                              void* d_out, int out_size) {
    const float* x_in    = (const float*)d_in[0];   // (2048,64,64)
    const int*   sub_adj = (const int*)  d_in[1];   // (64,64)
    const int*   adj     = (const int*)  d_in[2];   // (2048,2048)
    const float* W_convs = (const float*)d_in[3];   // (3,4,64,64)
    const float* b_convs = (const float*)d_in[4];   // (3,4,64)
    const float* ln_g    = (const float*)d_in[5];   // (3,64,64)
    const float* ln_b    = (const float*)d_in[6];   // (3,64,64)
    const float* W_lin   = (const float*)d_in[7];   // (4096,64)
    const float* b_lin   = (const float*)d_in[8];   // (64)
    float* out = (float*)d_out;

    float *Af, *AT, *A2, *A3, *X, *B1, *B2, *B3, *Sn;
    cudaGetSymbolAddress((void**)&Af, g_Af);
    cudaGetSymbolAddress((void**)&AT, g_AT);
    cudaGetSymbolAddress((void**)&A2, g_A2);
    cudaGetSymbolAddress((void**)&A3, g_A3);
    cudaGetSymbolAddress((void**)&X,  g_X);
    cudaGetSymbolAddress((void**)&B1, g_B1);
    cudaGetSymbolAddress((void**)&B2, g_B2);
    cudaGetSymbolAddress((void**)&B3, g_B3);
    cudaGetSymbolAddress((void**)&Sn, g_Sn);

    cudaFuncSetAttribute(gemm_tt, cudaFuncAttributeMaxDynamicSharedMemorySize,
                         GEMM_SMEM);
    cudaFuncSetAttribute(wsum_ln, cudaFuncAttributeMaxDynamicSharedMemorySize,
                         WSL_SMEM);

    // precompute: Af + AfT in one pass; (A^2)^T, (A^3)^T (exact int GEMMs); Sn
    cast_both<<<dim3(NN / 32, NN / 32), dim3(32, 8)>>>(adj, Af, AT);
    gemm_tt<<<dim3(NN / TBN, NN / TBM), 256, GEMM_SMEM>>>(Af, AT, A2, NN, NN, NN);
    gemm_tt<<<dim3(NN / TBN, NN / TBM), 256, GEMM_SMEM>>>(Af, A2, A3, NN, NN, NN);
    compute_sn<<<1, 256>>>(sub_adj, Sn);

    const dim3 gmeta(FDIM / TBN, NN / TBM);   // (32, 8)
    for (int l = 0; l < 3; l++) {
        const float* curX = (l == 0) ? x_in : X;
        const float* Wl = W_convs + (long)l * 4 * 4096;

        // x1 = A @ x ; x2 = A^2 @ x1 ; x3 = A^3 @ x2
        gemm_tt<<<gmeta, 256, GEMM_SMEM>>>(AT, curX, B1, NN, FDIM, NN);
        gemm_tt<<<gmeta, 256, GEMM_SMEM>>>(A2, B1,  B2, NN, FDIM, NN);
        gemm_tt<<<gmeta, 256, GEMM_SMEM>>>(A3, B2,  B3, NN, FDIM, NN);

        // X = relu(LN(Sn @ (sum_i xi Wi) + sum_i b_i))  — fully fused
        wsum_ln<<<(NN * MDIM) / 256, 256, WSL_SMEM>>>(curX, B1, B2, B3, Wl, Sn,
                                                      b_convs + (long)l * 256,
                                                      ln_g + (long)l * 4096,
                                                      ln_b + (long)l * 4096,
                                                      X);
    }

    final_gemm<<<NN / 16, 256>>>(X, W_lin, b_lin, out);
}